// round 1
// baseline (speedup 1.0000x reference)
#include <cuda_runtime.h>

// SSIM fused kernel for GB300 (sm_103a).
// out[b,c,i,j] = clip(1 - N/D, 0, 2) where
//   mu   = 3x3 mean of x / y
//   d**  = (center - mu)^2 terms, pooled again by 3x3 mean
// Two chained 3x3 box filters fused in one kernel via shared-memory staging.

#define C1f   (1.0e-4f)        // 0.01^2
#define NINE_C2f (8.1e-3f)     // 9 * 0.03^2

#define IMG_H 512
#define IMG_W 960
#define OUT_H 508
#define OUT_W 956

#define TW 64                  // output tile width
#define TH 16                  // output tile height
#define IW (TW + 4)            // 68 input tile width
#define IH (TH + 4)            // 20 input tile height
#define SW (TW + 2)            // 66 stage-1 width
#define SH (TH + 2)            // 18 stage-1 height
#define VH TH                  // 16 vertical-sum rows

#define NTHREADS 256

__global__ __launch_bounds__(NTHREADS)
void ssim_kernel(const float* __restrict__ X,
                 const float* __restrict__ Y,
                 float* __restrict__ O)
{
    __shared__ __align__(16) float sx[IH * IW];
    __shared__ __align__(16) float sy[IH * IW];
    __shared__ __align__(16) float s_mux[SH * SW];
    __shared__ __align__(16) float s_muy[SH * SW];
    __shared__ __align__(16) float s_dxx[SH * SW];
    __shared__ __align__(16) float s_dyy[SH * SW];
    __shared__ __align__(16) float s_dxy[SH * SW];
    __shared__ __align__(16) float s_vxx[VH * SW];
    __shared__ __align__(16) float s_vyy[VH * SW];
    __shared__ __align__(16) float s_vxy[VH * SW];

    const int tid = threadIdx.x;
    const int img = blockIdx.z;
    const int oy0 = blockIdx.y * TH;
    const int ox0 = blockIdx.x * TW;

    const float* __restrict__ Xb = X + (size_t)img * IMG_H * IMG_W;
    const float* __restrict__ Yb = Y + (size_t)img * IMG_H * IMG_W;

    // ---------------- Stage A: load halo tile of x, y into smem ------------
    #pragma unroll 4
    for (int i = tid; i < IH * IW; i += NTHREADS) {
        int r = i / IW;
        int c = i - r * IW;
        int iy = min(oy0 + r, IMG_H - 1);
        int ix = min(ox0 + c, IMG_W - 1);
        int g = iy * IMG_W + ix;
        sx[i] = Xb[g];
        sy[i] = Yb[g];
    }
    __syncthreads();

    // ---------------- Stage B: mu and d-products at 18 x 66 points ---------
    // Processed as float2 pairs of columns (c, c+1), c even. For each pair we
    // need x/y window rows r..r+2, cols c..c+3 (4 values = 2 float2 loads per
    // row). Centers (row r+1, cols c+1 / c+2) fall out of loaded registers.
    for (int i = tid; i < SH * (SW / 2); i += NTHREADS) {
        int r  = i / (SW / 2);
        int c2 = i - r * (SW / 2);
        int c  = 2 * c2;

        const float2* px = (const float2*)(sx + r * IW + c);
        const float2* py = (const float2*)(sy + r * IW + c);

        float2 a0 = px[0],          b0 = px[1];
        float2 a1 = px[IW / 2],     b1 = px[IW / 2 + 1];
        float2 a2 = px[IW],         b2 = px[IW + 1];

        float m0 = a0.y + b0.x;
        float m1 = a1.y + b1.x;
        float m2 = a2.y + b2.x;
        float Sx_lo = (a0.x + m0) + (a1.x + m1) + (a2.x + m2);
        float Sx_hi = (m0 + b0.y) + (m1 + b1.y) + (m2 + b2.y);
        float cx_lo = a1.y;   // x[r+1][c+1]
        float cx_hi = b1.x;   // x[r+1][c+2]

        float2 c0 = py[0],          d0 = py[1];
        float2 c1 = py[IW / 2],     d1 = py[IW / 2 + 1];
        float2 c2v = py[IW],        d2 = py[IW + 1];

        float n0 = c1.y + d1.x;
        float n0a = c0.y + d0.x;
        float n2 = c2v.y + d2.x;
        float Sy_lo = (c0.x + n0a) + (c1.x + n0) + (c2v.x + n2);
        float Sy_hi = (n0a + d0.y) + (n0 + d1.y) + (n2 + d2.y);
        float cy_lo = c1.y;
        float cy_hi = d1.x;

        const float inv9 = 1.0f / 9.0f;
        float mux_lo = Sx_lo * inv9, mux_hi = Sx_hi * inv9;
        float muy_lo = Sy_lo * inv9, muy_hi = Sy_hi * inv9;

        float dx_lo = cx_lo - mux_lo, dx_hi = cx_hi - mux_hi;
        float dy_lo = cy_lo - muy_lo, dy_hi = cy_hi - muy_hi;

        int o = r * SW + c;
        *(float2*)(s_mux + o) = make_float2(mux_lo, mux_hi);
        *(float2*)(s_muy + o) = make_float2(muy_lo, muy_hi);
        *(float2*)(s_dxx + o) = make_float2(dx_lo * dx_lo, dx_hi * dx_hi);
        *(float2*)(s_dyy + o) = make_float2(dy_lo * dy_lo, dy_hi * dy_hi);
        *(float2*)(s_dxy + o) = make_float2(dx_lo * dy_lo, dx_hi * dy_hi);
    }
    __syncthreads();

    // ---------------- Stage C: vertical 3-sums of d arrays -----------------
    for (int i = tid; i < VH * (SW / 2); i += NTHREADS) {
        int r  = i / (SW / 2);
        int c  = 2 * (i - r * (SW / 2));
        int o  = r * SW + c;

        float2 x0 = *(const float2*)(s_dxx + o);
        float2 x1 = *(const float2*)(s_dxx + o + SW);
        float2 x2 = *(const float2*)(s_dxx + o + 2 * SW);
        *(float2*)(s_vxx + o) = make_float2(x0.x + x1.x + x2.x, x0.y + x1.y + x2.y);

        float2 y0 = *(const float2*)(s_dyy + o);
        float2 y1 = *(const float2*)(s_dyy + o + SW);
        float2 y2 = *(const float2*)(s_dyy + o + 2 * SW);
        *(float2*)(s_vyy + o) = make_float2(y0.x + y1.x + y2.x, y0.y + y1.y + y2.y);

        float2 z0 = *(const float2*)(s_dxy + o);
        float2 z1 = *(const float2*)(s_dxy + o + SW);
        float2 z2 = *(const float2*)(s_dxy + o + 2 * SW);
        *(float2*)(s_vxy + o) = make_float2(z0.x + z1.x + z2.x, z0.y + z1.y + z2.y);
    }
    __syncthreads();

    // ---------------- Stage D: horizontal 3-sums + SSIM formula ------------
    for (int i = tid; i < TH * (TW / 2); i += NTHREADS) {
        int r = i / (TW / 2);
        int c = 2 * (i - r * (TW / 2));
        int o = r * SW + c;

        float2 p, q;
        p = *(const float2*)(s_vxx + o);  q = *(const float2*)(s_vxx + o + 2);
        float Sxx_lo = p.x + p.y + q.x, Sxx_hi = p.y + q.x + q.y;
        p = *(const float2*)(s_vyy + o);  q = *(const float2*)(s_vyy + o + 2);
        float Syy_lo = p.x + p.y + q.x, Syy_hi = p.y + q.x + q.y;
        p = *(const float2*)(s_vxy + o);  q = *(const float2*)(s_vxy + o + 2);
        float Sxy_lo = p.x + p.y + q.x, Sxy_hi = p.y + q.x + q.y;

        int om = (r + 1) * SW + (c + 1);
        float mux_lo = s_mux[om],     mux_hi = s_mux[om + 1];
        float muy_lo = s_muy[om],     muy_hi = s_muy[om + 1];

        // (2*mu_x*mu_y + C1)(2*Sxy/9 + C2)  /  (mu_x^2+mu_y^2+C1)(Sxx/9+Syy/9+C2)
        // the 1/9 factors cancel between numerator and denominator:
        float num_lo = (2.0f * mux_lo * muy_lo + C1f) * (2.0f * Sxy_lo + NINE_C2f);
        float den_lo = (mux_lo * mux_lo + muy_lo * muy_lo + C1f) * (Sxx_lo + Syy_lo + NINE_C2f);
        float out_lo = 1.0f - __fdividef(num_lo, den_lo);
        out_lo = fminf(fmaxf(out_lo, 0.0f), 2.0f);

        float num_hi = (2.0f * mux_hi * muy_hi + C1f) * (2.0f * Sxy_hi + NINE_C2f);
        float den_hi = (mux_hi * mux_hi + muy_hi * muy_hi + C1f) * (Sxx_hi + Syy_hi + NINE_C2f);
        float out_hi = 1.0f - __fdividef(num_hi, den_hi);
        out_hi = fminf(fmaxf(out_hi, 0.0f), 2.0f);

        int oy = oy0 + r;
        int ox = ox0 + c;
        if (oy < OUT_H && ox < OUT_W) {
            // ox even, OUT_W even -> ox+1 also in range; 8B-aligned store.
            float* dst = O + (size_t)img * OUT_H * OUT_W + (size_t)oy * OUT_W + ox;
            *(float2*)dst = make_float2(out_lo, out_hi);
        }
    }
}

extern "C" void kernel_launch(void* const* d_in, const int* in_sizes, int n_in,
                              void* d_out, int out_size)
{
    const float* x = (const float*)d_in[0];
    const float* y = (const float*)d_in[1];
    float* o = (float*)d_out;

    dim3 grid((OUT_W + TW - 1) / TW,   // 15
              (OUT_H + TH - 1) / TH,   // 32
              48);                     // 16 batch * 3 channels
    ssim_kernel<<<grid, NTHREADS>>>(x, y, o);
}

// round 2
// speedup vs baseline: 1.3163x; 1.3163x over previous
#include <cuda_runtime.h>

// SSIM fully-fused kernel for GB300 (sm_103a).
// Register-sliding over rows: only the x/y input tiles live in shared memory;
// both chained 3x3 box filters are computed in registers using ring buffers,
// with packed f32x2 arithmetic (2x fp32 throughput on sm_103a).
//
// Algebraic rescale: with S = 3x3 sum and u = S - 9*xc,
//   xc - mu = -u/9,  sigma-sums = U/729 where U = 3x3 sum of u-products.
// All 1/9, 1/81, 1/729 factors cancel between numerator and denominator:
//   num = (2*Sx*Sy + 81*C1) * (2*Uxy + 729*C2)
//   den = (Sx^2 + Sy^2 + 81*C1) * (Uxx + Uyy + 729*C2)
//   out = clip(1 - num/den, 0, 2)

#define IMG_H 512
#define IMG_W 960
#define OUT_H 508
#define OUT_W 956

#define TILE_W 128           // output cols per CTA (64 threads x 2 cols)
#define TILE_H 64            // output rows per CTA (4 strips x 16 rows)
#define STRIP_H 16
#define IWT (TILE_W + 4)     // 132 input cols in tile
#define IHT (TILE_H + 4)     // 68  input rows in tile
#define NTHREADS 256
#define SMEM_BYTES (2 * IHT * IWT * 4)   // 71808

typedef unsigned long long u64;

__device__ __forceinline__ u64 PK(float lo, float hi) {
    u64 r; asm("mov.b64 %0, {%1, %2};" : "=l"(r) : "f"(lo), "f"(hi)); return r;
}
__device__ __forceinline__ void UPK(u64 a, float& lo, float& hi) {
    asm("mov.b64 {%0, %1}, %2;" : "=f"(lo), "=f"(hi) : "l"(a));
}
// (a.hi, b.lo)
__device__ __forceinline__ u64 SHP(u64 a, u64 b) {
    float alo, ahi, blo, bhi; UPK(a, alo, ahi); UPK(b, blo, bhi);
    return PK(ahi, blo);
}
__device__ __forceinline__ u64 PADD(u64 a, u64 b) {
    u64 r; asm("add.rn.f32x2 %0, %1, %2;" : "=l"(r) : "l"(a), "l"(b)); return r;
}
__device__ __forceinline__ u64 PMUL(u64 a, u64 b) {
    u64 r; asm("mul.rn.f32x2 %0, %1, %2;" : "=l"(r) : "l"(a), "l"(b)); return r;
}
__device__ __forceinline__ u64 PFMA(u64 a, u64 b, u64 c) {
    u64 r; asm("fma.rn.f32x2 %0, %1, %2, %3;" : "=l"(r) : "l"(a), "l"(b), "l"(c)); return r;
}

extern __shared__ float smem_dyn[];

__global__ __launch_bounds__(NTHREADS)
void ssim_kernel(const float* __restrict__ X,
                 const float* __restrict__ Y,
                 float* __restrict__ O)
{
    float* __restrict__ sx = smem_dyn;
    float* __restrict__ sy = smem_dyn + IHT * IWT;

    const int tid = threadIdx.x;
    const int img = blockIdx.z;
    const int oy0 = blockIdx.y * TILE_H;
    const int ox0 = blockIdx.x * TILE_W;

    const float* __restrict__ Xb = X + (size_t)img * (IMG_H * IMG_W);
    const float* __restrict__ Yb = Y + (size_t)img * (IMG_H * IMG_W);

    // ---- Stage A: load (clamped) input halo tile into smem -----------------
    #pragma unroll 4
    for (int i = tid; i < IHT * IWT; i += NTHREADS) {
        int r = i / IWT;
        int c = i - r * IWT;
        int gy = min(oy0 + r, IMG_H - 1);
        int gx = min(ox0 + c, IMG_W - 1);
        size_t g = (size_t)gy * IMG_W + gx;
        sx[i] = __ldg(Xb + g);
        sy[i] = __ldg(Yb + g);
    }
    __syncthreads();

    // ---- Register-sliding compute ------------------------------------------
    const int tx = tid & 63;        // output column pair within tile
    const int ty = tid >> 6;        // vertical strip
    const int oc = 2 * tx;          // tile-local output col (even)
    const int r0 = ty * STRIP_H;    // first tile-local input row of this strip
    const int ox = ox0 + oc;
    const bool col_ok = (ox < OUT_W);   // ox even, OUT_W even -> ox+1 ok too

    const u64 c_m9    = PK(-9.0f, -9.0f);
    const u64 c_two   = PK(2.0f, 2.0f);
    const u64 c_81c1  = PK(8.1e-3f, 8.1e-3f);     // 81 * 0.01^2
    const u64 c_729c2 = PK(0.6561f, 0.6561f);     // 729 * 0.03^2

    // Ring buffers: summing all 3 slots == vertical 3-sum (rotation-invariant).
    u64 hx0[3], hx1[3], hy0[3], hy1[3];    // horizontal 3-sums, 2 col-pairs
    u64 Hxx[3], Hyy[3], Hxy[3];            // stage-2 horizontal sums
    u64 cpx0 = 0, cpx1 = 0, cpy0 = 0, cpy1 = 0;   // prev-row center pairs
    u64 smx_prev = 0, smy_prev = 0;                // mu-sums, 1-row history

    float* __restrict__ Ob = O + (size_t)img * (OUT_H * OUT_W);

    #pragma unroll
    for (int t = 0; t < STRIP_H + 4; ++t) {
        const int ir = r0 + t;
        const float* rowx = sx + ir * IWT + oc;
        const float* rowy = sy + ir * IWT + oc;
        float2 Axv = *(const float2*)(rowx);
        float2 Bxv = *(const float2*)(rowx + 2);
        float2 Cxv = *(const float2*)(rowx + 4);
        float2 Ayv = *(const float2*)(rowy);
        float2 Byv = *(const float2*)(rowy + 2);
        float2 Cyv = *(const float2*)(rowy + 4);

        u64 PAx = PK(Axv.x, Axv.y), PBx = PK(Bxv.x, Bxv.y), PCx = PK(Cxv.x, Cxv.y);
        u64 sh0x = PK(Axv.y, Bxv.x), sh1x = PK(Bxv.y, Cxv.x);
        u64 PAy = PK(Ayv.x, Ayv.y), PBy = PK(Byv.x, Byv.y), PCy = PK(Cyv.x, Cyv.y);
        u64 sh0y = PK(Ayv.y, Byv.x), sh1y = PK(Byv.y, Cyv.x);

        const int slot = t % 3;
        // horizontal 3-sums at stage-1 cols (oc,oc+1) and (oc+2,oc+3)
        hx0[slot] = PADD(PADD(PAx, sh0x), PBx);
        hx1[slot] = PADD(PADD(PBx, sh1x), PCx);
        hy0[slot] = PADD(PADD(PAy, sh0y), PBy);
        hy1[slot] = PADD(PADD(PBy, sh1y), PCy);

        if (t >= 2) {
            // stage-1 row i1 = ir-2: vertical sums over all 3 ring slots
            u64 Sx0 = PADD(PADD(hx0[0], hx0[1]), hx0[2]);
            u64 Sx1 = PADD(PADD(hx1[0], hx1[1]), hx1[2]);
            u64 Sy0 = PADD(PADD(hy0[0], hy0[1]), hy0[2]);
            u64 Sy1 = PADD(PADD(hy1[0], hy1[1]), hy1[2]);

            // u = S - 9*center   (center = prev row values at cols+1)
            u64 ux0 = PFMA(cpx0, c_m9, Sx0);
            u64 ux1 = PFMA(cpx1, c_m9, Sx1);
            u64 uy0 = PFMA(cpy0, c_m9, Sy0);
            u64 uy1 = PFMA(cpy1, c_m9, Sy1);

            u64 txx0 = PMUL(ux0, ux0), txx1 = PMUL(ux1, ux1);
            u64 tyy0 = PMUL(uy0, uy0), tyy1 = PMUL(uy1, uy1);
            u64 txy0 = PMUL(ux0, uy0), txy1 = PMUL(ux1, uy1);

            // stage-2 horizontal 3-sums for the two output columns
            Hxx[slot] = PADD(PADD(txx0, SHP(txx0, txx1)), txx1);
            Hyy[slot] = PADD(PADD(tyy0, SHP(tyy0, tyy1)), tyy1);
            Hxy[slot] = PADD(PADD(txy0, SHP(txy0, txy1)), txy1);

            if (t >= 4) {
                // output row o = ir-4 uses stage-1 rows ir-4..ir-2 (all slots)
                u64 Uxx = PADD(PADD(Hxx[0], Hxx[1]), Hxx[2]);
                u64 Uyy = PADD(PADD(Hyy[0], Hyy[1]), Hyy[2]);
                u64 Uxy = PADD(PADD(Hxy[0], Hxy[1]), Hxy[2]);

                // mu terms: stage-1 row o+1 = ir-3 -> previous step's Smid
                u64 SxSy = PMUL(smx_prev, smy_prev);
                u64 n1 = PFMA(SxSy, c_two, c_81c1);
                u64 d1 = PFMA(smy_prev, smy_prev,
                              PFMA(smx_prev, smx_prev, c_81c1));
                u64 n2 = PFMA(Uxy, c_two, c_729c2);
                u64 d2 = PADD(PADD(Uxx, Uyy), c_729c2);
                u64 num = PMUL(n1, n2);
                u64 den = PMUL(d1, d2);

                float nlo, nhi, dlo, dhi;
                UPK(num, nlo, nhi); UPK(den, dlo, dhi);
                float olo = 1.0f - __fdividef(nlo, dlo);
                float ohi = 1.0f - __fdividef(nhi, dhi);
                olo = fminf(fmaxf(olo, 0.0f), 2.0f);
                ohi = fminf(fmaxf(ohi, 0.0f), 2.0f);

                int oy = oy0 + r0 + (t - 4);
                if (col_ok && oy < OUT_H) {
                    *(float2*)(Ob + (size_t)oy * OUT_W + ox) =
                        make_float2(olo, ohi);
                }
            }

            // Smid for this stage-1 row (cols oc+1, oc+2) -> used next step
            smx_prev = SHP(Sx0, Sx1);
            smy_prev = SHP(Sy0, Sy1);
        }

        // centers for next step's stage-1 row = this row's shifted pairs
        cpx0 = sh0x; cpx1 = sh1x;
        cpy0 = sh0y; cpy1 = sh1y;
    }
}

extern "C" void kernel_launch(void* const* d_in, const int* in_sizes, int n_in,
                              void* d_out, int out_size)
{
    const float* x = (const float*)d_in[0];
    const float* y = (const float*)d_in[1];
    float* o = (float*)d_out;

    cudaFuncSetAttribute(ssim_kernel,
                         cudaFuncAttributeMaxDynamicSharedMemorySize,
                         SMEM_BYTES);

    dim3 grid((OUT_W + TILE_W - 1) / TILE_W,   // 8
              (OUT_H + TILE_H - 1) / TILE_H,   // 8
              48);                             // 16 batch * 3 channels
    ssim_kernel<<<grid, NTHREADS, SMEM_BYTES>>>(x, y, o);
}

// round 3
// speedup vs baseline: 1.9532x; 1.4839x over previous
#include <cuda_runtime.h>

// SSIM fully-fused, smem-free kernel for GB300 (sm_103a).
// Each thread produces a 4-column x 16-row output patch by sliding vertically,
// reading 2 float4 per input array per row directly from global (L1-cached;
// vertical reuse lives in register ring buffers, horizontal reuse hits the
// same 128B lines within the warp). All math in packed f32x2.
//
// Algebra (scale-cancelled): with S = 3x3 sum, u = S - 9*center,
//   num = (2*Sx*Sy + 81*C1) * (2*Uxy + 729*C2)
//   den = (Sx^2 + Sy^2 + 81*C1) * (Uxx + Uyy + 729*C2)
//   out = clip(1 - num/den, 0, 2)

#define IMG_H 512
#define IMG_W 960
#define OUT_H 508
#define OUT_W 956

#define NTHREADS 128          // 32 lanes wide x 4 strips
#define STRIP_H 16
#define TILE_W 128            // 32 lanes x 4 cols
#define TILE_H 64             // 4 strips x 16 rows

typedef unsigned long long u64;

__device__ __forceinline__ u64 PK(float lo, float hi) {
    u64 r; asm("mov.b64 %0, {%1, %2};" : "=l"(r) : "f"(lo), "f"(hi)); return r;
}
__device__ __forceinline__ void UPK(u64 a, float& lo, float& hi) {
    asm("mov.b64 {%0, %1}, %2;" : "=f"(lo), "=f"(hi) : "l"(a));
}
// (a.hi, b.lo)
__device__ __forceinline__ u64 SHP(u64 a, u64 b) {
    float alo, ahi, blo, bhi; UPK(a, alo, ahi); UPK(b, blo, bhi);
    return PK(ahi, blo);
}
__device__ __forceinline__ u64 PADD(u64 a, u64 b) {
    u64 r; asm("add.rn.f32x2 %0, %1, %2;" : "=l"(r) : "l"(a), "l"(b)); return r;
}
__device__ __forceinline__ u64 PMUL(u64 a, u64 b) {
    u64 r; asm("mul.rn.f32x2 %0, %1, %2;" : "=l"(r) : "l"(a), "l"(b)); return r;
}
__device__ __forceinline__ u64 PFMA(u64 a, u64 b, u64 c) {
    u64 r; asm("fma.rn.f32x2 %0, %1, %2, %3;" : "=l"(r) : "l"(a), "l"(b), "l"(c)); return r;
}

__global__ __launch_bounds__(NTHREADS)
void ssim_kernel(const float* __restrict__ X,
                 const float* __restrict__ Y,
                 float* __restrict__ O)
{
    const int tid   = threadIdx.x;
    const int lane  = tid & 31;
    const int strip = tid >> 5;
    const int img   = blockIdx.z;
    const int oy0   = blockIdx.y * TILE_H + strip * STRIP_H;
    const int ox    = blockIdx.x * TILE_W + 4 * lane;
    // Clamp read base so edge threads stay in-bounds (their outputs are
    // discarded by the ox < OUT_W guard). 952 = IMG_W - 8, multiple of 4.
    const int cx    = min(ox, IMG_W - 8);

    const float* __restrict__ Xb = X + (size_t)img * (IMG_H * IMG_W) + cx;
    const float* __restrict__ Yb = Y + (size_t)img * (IMG_H * IMG_W) + cx;
    float* __restrict__ Ob = O + (size_t)img * (OUT_H * OUT_W);

    const u64 c_m9    = PK(-9.0f, -9.0f);
    const u64 c_two   = PK(2.0f, 2.0f);
    const u64 c_81c1  = PK(8.1e-3f, 8.1e-3f);     // 81 * 0.01^2
    const u64 c_729c2 = PK(0.6561f, 0.6561f);     // 729 * 0.03^2

    // Ring buffers (summing all 3 slots == vertical 3-sum).
    u64 hx0[3], hx1[3], hx2[3], hy0[3], hy1[3], hy2[3];
    u64 Hxx0[3], Hxx1[3], Hyy0[3], Hyy1[3], Hxy0[3], Hxy1[3];
    // Previous-row shifted pairs (centers for u = S - 9*c).
    u64 pXS0 = 0, pXS1 = 0, pXS2 = 0, pYS0 = 0, pYS1 = 0, pYS2 = 0;
    // mu sums from previous stage-1 row.
    u64 smx0 = 0, smx1 = 0, smy0 = 0, smy1 = 0;

    #pragma unroll
    for (int t = 0; t < STRIP_H + 4; ++t) {
        const int gy = min(oy0 + t, IMG_H - 1);
        const size_t roff = (size_t)gy * IMG_W;

        float4 xa = __ldg((const float4*)(Xb + roff));
        float4 xb = __ldg((const float4*)(Xb + roff) + 1);
        float4 ya = __ldg((const float4*)(Yb + roff));
        float4 yb = __ldg((const float4*)(Yb + roff) + 1);

        // natural pairs P_i = (v2i, v2i+1), shifted S_i = (v2i+1, v2i+2)
        u64 XP0 = PK(xa.x, xa.y), XS0 = PK(xa.y, xa.z), XP1 = PK(xa.z, xa.w);
        u64 XS1 = PK(xa.w, xb.x), XP2 = PK(xb.x, xb.y), XS2 = PK(xb.y, xb.z);
        u64 XP3 = PK(xb.z, xb.w);
        u64 YP0 = PK(ya.x, ya.y), YS0 = PK(ya.y, ya.z), YP1 = PK(ya.z, ya.w);
        u64 YS1 = PK(ya.w, yb.x), YP2 = PK(yb.x, yb.y), YS2 = PK(yb.y, yb.z);
        u64 YP3 = PK(yb.z, yb.w);

        const int slot = t % 3;
        // horizontal 3-sums at stage-1 col pairs (oc,+1),(+2,+3),(+4,+5)
        hx0[slot] = PADD(PADD(XP0, XS0), XP1);
        hx1[slot] = PADD(PADD(XP1, XS1), XP2);
        hx2[slot] = PADD(PADD(XP2, XS2), XP3);
        hy0[slot] = PADD(PADD(YP0, YS0), YP1);
        hy1[slot] = PADD(PADD(YP1, YS1), YP2);
        hy2[slot] = PADD(PADD(YP2, YS2), YP3);

        if (t >= 2) {
            // stage-1 row i1 = gy-2: vertical 3-sums
            u64 Sx0 = PADD(PADD(hx0[0], hx0[1]), hx0[2]);
            u64 Sx1 = PADD(PADD(hx1[0], hx1[1]), hx1[2]);
            u64 Sx2 = PADD(PADD(hx2[0], hx2[1]), hx2[2]);
            u64 Sy0 = PADD(PADD(hy0[0], hy0[1]), hy0[2]);
            u64 Sy1 = PADD(PADD(hy1[0], hy1[1]), hy1[2]);
            u64 Sy2 = PADD(PADD(hy2[0], hy2[1]), hy2[2]);

            // u = S - 9*center (centers = prev row shifted pairs, cols +1)
            u64 ux0 = PFMA(pXS0, c_m9, Sx0);
            u64 ux1 = PFMA(pXS1, c_m9, Sx1);
            u64 ux2 = PFMA(pXS2, c_m9, Sx2);
            u64 uy0 = PFMA(pYS0, c_m9, Sy0);
            u64 uy1 = PFMA(pYS1, c_m9, Sy1);
            u64 uy2 = PFMA(pYS2, c_m9, Sy2);

            u64 txx0 = PMUL(ux0, ux0), txx1 = PMUL(ux1, ux1), txx2 = PMUL(ux2, ux2);
            u64 tyy0 = PMUL(uy0, uy0), tyy1 = PMUL(uy1, uy1), tyy2 = PMUL(uy2, uy2);
            u64 txy0 = PMUL(ux0, uy0), txy1 = PMUL(ux1, uy1), txy2 = PMUL(ux2, uy2);

            // stage-2 horizontal 3-sums for output pairs (oc,+1) and (+2,+3)
            Hxx0[slot] = PADD(PADD(txx0, SHP(txx0, txx1)), txx1);
            Hxx1[slot] = PADD(PADD(txx1, SHP(txx1, txx2)), txx2);
            Hyy0[slot] = PADD(PADD(tyy0, SHP(tyy0, tyy1)), tyy1);
            Hyy1[slot] = PADD(PADD(tyy1, SHP(tyy1, tyy2)), tyy2);
            Hxy0[slot] = PADD(PADD(txy0, SHP(txy0, txy1)), txy1);
            Hxy1[slot] = PADD(PADD(txy1, SHP(txy1, txy2)), txy2);

            if (t >= 4) {
                // output row o = (oy0+t)-4; stage-2 vertical sums
                u64 Uxx0 = PADD(PADD(Hxx0[0], Hxx0[1]), Hxx0[2]);
                u64 Uxx1 = PADD(PADD(Hxx1[0], Hxx1[1]), Hxx1[2]);
                u64 Uyy0 = PADD(PADD(Hyy0[0], Hyy0[1]), Hyy0[2]);
                u64 Uyy1 = PADD(PADD(Hyy1[0], Hyy1[1]), Hyy1[2]);
                u64 Uxy0 = PADD(PADD(Hxy0[0], Hxy0[1]), Hxy0[2]);
                u64 Uxy1 = PADD(PADD(Hxy1[0], Hxy1[1]), Hxy1[2]);

                // mu sums from previous iteration (stage-1 row o+1)
                u64 n1a = PFMA(PMUL(smx0, smy0), c_two, c_81c1);
                u64 d1a = PFMA(smy0, smy0, PFMA(smx0, smx0, c_81c1));
                u64 n1b = PFMA(PMUL(smx1, smy1), c_two, c_81c1);
                u64 d1b = PFMA(smy1, smy1, PFMA(smx1, smx1, c_81c1));

                u64 n2a = PFMA(Uxy0, c_two, c_729c2);
                u64 d2a = PADD(PADD(Uxx0, Uyy0), c_729c2);
                u64 n2b = PFMA(Uxy1, c_two, c_729c2);
                u64 d2b = PADD(PADD(Uxx1, Uyy1), c_729c2);

                u64 numa = PMUL(n1a, n2a), dena = PMUL(d1a, d2a);
                u64 numb = PMUL(n1b, n2b), denb = PMUL(d1b, d2b);

                float n0, n1, n2, n3, d0, d1, d2, d3;
                UPK(numa, n0, n1); UPK(numb, n2, n3);
                UPK(dena, d0, d1); UPK(denb, d2, d3);
                float4 out;
                out.x = fminf(fmaxf(1.0f - __fdividef(n0, d0), 0.0f), 2.0f);
                out.y = fminf(fmaxf(1.0f - __fdividef(n1, d1), 0.0f), 2.0f);
                out.z = fminf(fmaxf(1.0f - __fdividef(n2, d2), 0.0f), 2.0f);
                out.w = fminf(fmaxf(1.0f - __fdividef(n3, d3), 0.0f), 2.0f);

                const int oy = oy0 + t - 4;
                if (oy < OUT_H && ox < OUT_W) {
                    *(float4*)(Ob + (size_t)oy * OUT_W + ox) = out;
                }
            }

            // mu sums for next iteration's output (cols +1 of stage-1 pairs)
            smx0 = SHP(Sx0, Sx1); smx1 = SHP(Sx1, Sx2);
            smy0 = SHP(Sy0, Sy1); smy1 = SHP(Sy1, Sy2);
        }

        // centers for the next stage-1 row
        pXS0 = XS0; pXS1 = XS1; pXS2 = XS2;
        pYS0 = YS0; pYS1 = YS1; pYS2 = YS2;
    }
}

extern "C" void kernel_launch(void* const* d_in, const int* in_sizes, int n_in,
                              void* d_out, int out_size)
{
    const float* x = (const float*)d_in[0];
    const float* y = (const float*)d_in[1];
    float* o = (float*)d_out;

    dim3 grid((OUT_W + TILE_W - 1) / TILE_W,   // 8
              (OUT_H + TILE_H - 1) / TILE_H,   // 8
              48);                             // 16 batch * 3 channels
    ssim_kernel<<<grid, NTHREADS>>>(x, y, o);
}

// round 4
// speedup vs baseline: 2.5707x; 1.3161x over previous
#include <cuda_runtime.h>

// SSIM fully-fused, smem-free kernel for GB300 (sm_103a).
// Each thread produces a 4-column x 16-row output patch by sliding vertically,
// reading 2 float4 per input array per row directly from global. Vertical
// reuse lives in (prev, pairsum) register accumulators (2 regs per running
// 3-sum instead of a 3-slot ring), all math in packed f32x2.
//
// Algebra (scale-cancelled): with S = 3x3 sum, u = S - 9*center,
//   num = (2*Sx*Sy + 81*C1) * (2*Uxy + 729*C2)
//   den = (Sx^2 + Sy^2 + 81*C1) * (Uxx + Uyy + 729*C2)
//   out = clip(1 - num/den, 0, 2)

#define IMG_H 512
#define IMG_W 960
#define OUT_H 508
#define OUT_W 956

#define NTHREADS 128          // 32 lanes wide x 4 strips
#define STRIP_H 16
#define TILE_W 128            // 32 lanes x 4 cols
#define TILE_H 64             // 4 strips x 16 rows

typedef unsigned long long u64;

__device__ __forceinline__ u64 PK(float lo, float hi) {
    u64 r; asm("mov.b64 %0, {%1, %2};" : "=l"(r) : "f"(lo), "f"(hi)); return r;
}
__device__ __forceinline__ void UPK(u64 a, float& lo, float& hi) {
    asm("mov.b64 {%0, %1}, %2;" : "=f"(lo), "=f"(hi) : "l"(a));
}
// (a.hi, b.lo)
__device__ __forceinline__ u64 SHP(u64 a, u64 b) {
    float alo, ahi, blo, bhi; UPK(a, alo, ahi); UPK(b, blo, bhi);
    return PK(ahi, blo);
}
__device__ __forceinline__ u64 PADD(u64 a, u64 b) {
    u64 r; asm("add.rn.f32x2 %0, %1, %2;" : "=l"(r) : "l"(a), "l"(b)); return r;
}
__device__ __forceinline__ u64 PMUL(u64 a, u64 b) {
    u64 r; asm("mul.rn.f32x2 %0, %1, %2;" : "=l"(r) : "l"(a), "l"(b)); return r;
}
__device__ __forceinline__ u64 PFMA(u64 a, u64 b, u64 c) {
    u64 r; asm("fma.rn.f32x2 %0, %1, %2, %3;" : "=l"(r) : "l"(a), "l"(b), "l"(c)); return r;
}
#define PREF_L2(p) asm volatile("prefetch.global.L2 [%0];" :: "l"(p))

__global__ __launch_bounds__(NTHREADS, 4)
void ssim_kernel(const float* __restrict__ X,
                 const float* __restrict__ Y,
                 float* __restrict__ O)
{
    const int tid   = threadIdx.x;
    const int lane  = tid & 31;
    const int strip = tid >> 5;
    const int img   = blockIdx.z;
    const int oy0   = blockIdx.y * TILE_H + strip * STRIP_H;
    const int ox    = blockIdx.x * TILE_W + 4 * lane;
    // Clamp read base so edge threads stay in-bounds (outputs masked later).
    const int cx    = min(ox, IMG_W - 8);

    const float* __restrict__ Xb = X + (size_t)img * (IMG_H * IMG_W) + cx;
    const float* __restrict__ Yb = Y + (size_t)img * (IMG_H * IMG_W) + cx;
    float* __restrict__ Ob = O + (size_t)img * (OUT_H * OUT_W);

    const u64 c_m9    = PK(-9.0f, -9.0f);
    const u64 c_two   = PK(2.0f, 2.0f);
    const u64 c_81c1  = PK(8.1e-3f, 8.1e-3f);     // 81 * 0.01^2
    const u64 c_729c2 = PK(0.6561f, 0.6561f);     // 729 * 0.03^2

    // (prev, pairsum) accumulators: running vertical 3-sum state, 2 regs each.
    u64 hx0p = 0, hx0s = 0, hx1p = 0, hx1s = 0, hx2p = 0, hx2s = 0;
    u64 hy0p = 0, hy0s = 0, hy1p = 0, hy1s = 0, hy2p = 0, hy2s = 0;
    u64 Hxx0p = 0, Hxx0s = 0, Hxx1p = 0, Hxx1s = 0;
    u64 Hyy0p = 0, Hyy0s = 0, Hyy1p = 0, Hyy1s = 0;
    u64 Hxy0p = 0, Hxy0s = 0, Hxy1p = 0, Hxy1s = 0;
    // Previous-row shifted pairs (centers for u = S - 9*c).
    u64 pXS0 = 0, pXS1 = 0, pXS2 = 0, pYS0 = 0, pYS1 = 0, pYS2 = 0;
    // mu sums from previous stage-1 row.
    u64 smx0 = 0, smx1 = 0, smy0 = 0, smy1 = 0;

    #pragma unroll
    for (int t = 0; t < STRIP_H + 4; ++t) {
        const int gy = min(oy0 + t, IMG_H - 1);
        const size_t roff = (size_t)gy * IMG_W;

        float4 xa = __ldg((const float4*)(Xb + roff));
        float4 xb = __ldg((const float4*)(Xb + roff) + 1);
        float4 ya = __ldg((const float4*)(Yb + roff));
        float4 yb = __ldg((const float4*)(Yb + roff) + 1);

        if (t + 4 < STRIP_H + 4) {   // compile-time under full unroll
            const size_t poff = (size_t)min(oy0 + t + 4, IMG_H - 1) * IMG_W;
            PREF_L2(Xb + poff);
            PREF_L2(Yb + poff);
        }

        // natural pairs P_i = (v2i, v2i+1), shifted S_i = (v2i+1, v2i+2)
        u64 XP0 = PK(xa.x, xa.y), XS0 = PK(xa.y, xa.z), XP1 = PK(xa.z, xa.w);
        u64 XS1 = PK(xa.w, xb.x), XP2 = PK(xb.x, xb.y), XS2 = PK(xb.y, xb.z);
        u64 XP3 = PK(xb.z, xb.w);
        u64 YP0 = PK(ya.x, ya.y), YS0 = PK(ya.y, ya.z), YP1 = PK(ya.z, ya.w);
        u64 YS1 = PK(ya.w, yb.x), YP2 = PK(yb.x, yb.y), YS2 = PK(yb.y, yb.z);
        u64 YP3 = PK(yb.z, yb.w);

        // horizontal 3-sums at stage-1 col pairs (0,1),(2,3),(4,5)
        u64 nhx0 = PADD(PADD(XP0, XS0), XP1);
        u64 nhx1 = PADD(PADD(XP1, XS1), XP2);
        u64 nhx2 = PADD(PADD(XP2, XS2), XP3);
        u64 nhy0 = PADD(PADD(YP0, YS0), YP1);
        u64 nhy1 = PADD(PADD(YP1, YS1), YP2);
        u64 nhy2 = PADD(PADD(YP2, YS2), YP3);

        if (t >= 2) {
            // stage-1 vertical 3-sums: S = h_t + (h_{t-1} + h_{t-2})
            u64 Sx0 = PADD(nhx0, hx0s);
            u64 Sx1 = PADD(nhx1, hx1s);
            u64 Sx2 = PADD(nhx2, hx2s);
            u64 Sy0 = PADD(nhy0, hy0s);
            u64 Sy1 = PADD(nhy1, hy1s);
            u64 Sy2 = PADD(nhy2, hy2s);

            // u = S - 9*center (centers = prev row shifted pairs)
            u64 ux0 = PFMA(pXS0, c_m9, Sx0);
            u64 ux1 = PFMA(pXS1, c_m9, Sx1);
            u64 ux2 = PFMA(pXS2, c_m9, Sx2);
            u64 uy0 = PFMA(pYS0, c_m9, Sy0);
            u64 uy1 = PFMA(pYS1, c_m9, Sy1);
            u64 uy2 = PFMA(pYS2, c_m9, Sy2);

            u64 txx0 = PMUL(ux0, ux0), txx1 = PMUL(ux1, ux1), txx2 = PMUL(ux2, ux2);
            u64 tyy0 = PMUL(uy0, uy0), tyy1 = PMUL(uy1, uy1), tyy2 = PMUL(uy2, uy2);
            u64 txy0 = PMUL(ux0, uy0), txy1 = PMUL(ux1, uy1), txy2 = PMUL(ux2, uy2);

            // stage-2 horizontal 3-sums for output pairs (0,1) and (2,3)
            u64 nHxx0 = PADD(PADD(txx0, SHP(txx0, txx1)), txx1);
            u64 nHxx1 = PADD(PADD(txx1, SHP(txx1, txx2)), txx2);
            u64 nHyy0 = PADD(PADD(tyy0, SHP(tyy0, tyy1)), tyy1);
            u64 nHyy1 = PADD(PADD(tyy1, SHP(tyy1, tyy2)), tyy2);
            u64 nHxy0 = PADD(PADD(txy0, SHP(txy0, txy1)), txy1);
            u64 nHxy1 = PADD(PADD(txy1, SHP(txy1, txy2)), txy2);

            if (t >= 4) {
                // stage-2 vertical 3-sums: U = H_t + (H_{t-1} + H_{t-2})
                u64 Uxx0 = PADD(nHxx0, Hxx0s);
                u64 Uxx1 = PADD(nHxx1, Hxx1s);
                u64 Uyy0 = PADD(nHyy0, Hyy0s);
                u64 Uyy1 = PADD(nHyy1, Hyy1s);
                u64 Uxy0 = PADD(nHxy0, Hxy0s);
                u64 Uxy1 = PADD(nHxy1, Hxy1s);

                // mu sums from previous iteration (stage-1 row o+1)
                u64 n1a = PFMA(PMUL(smx0, smy0), c_two, c_81c1);
                u64 d1a = PFMA(smy0, smy0, PFMA(smx0, smx0, c_81c1));
                u64 n1b = PFMA(PMUL(smx1, smy1), c_two, c_81c1);
                u64 d1b = PFMA(smy1, smy1, PFMA(smx1, smx1, c_81c1));

                u64 n2a = PFMA(Uxy0, c_two, c_729c2);
                u64 d2a = PADD(PADD(Uxx0, Uyy0), c_729c2);
                u64 n2b = PFMA(Uxy1, c_two, c_729c2);
                u64 d2b = PADD(PADD(Uxx1, Uyy1), c_729c2);

                u64 numa = PMUL(n1a, n2a), dena = PMUL(d1a, d2a);
                u64 numb = PMUL(n1b, n2b), denb = PMUL(d1b, d2b);

                float n0, n1, n2, n3, d0, d1, d2, d3;
                UPK(numa, n0, n1); UPK(numb, n2, n3);
                UPK(dena, d0, d1); UPK(denb, d2, d3);
                float4 out;
                out.x = fminf(fmaxf(1.0f - __fdividef(n0, d0), 0.0f), 2.0f);
                out.y = fminf(fmaxf(1.0f - __fdividef(n1, d1), 0.0f), 2.0f);
                out.z = fminf(fmaxf(1.0f - __fdividef(n2, d2), 0.0f), 2.0f);
                out.w = fminf(fmaxf(1.0f - __fdividef(n3, d3), 0.0f), 2.0f);

                const int oy = oy0 + t - 4;
                if (oy < OUT_H && ox < OUT_W) {
                    *(float4*)(Ob + (size_t)oy * OUT_W + ox) = out;
                }
            }

            // stage-2 accumulator updates
            Hxx0s = PADD(nHxx0, Hxx0p);  Hxx0p = nHxx0;
            Hxx1s = PADD(nHxx1, Hxx1p);  Hxx1p = nHxx1;
            Hyy0s = PADD(nHyy0, Hyy0p);  Hyy0p = nHyy0;
            Hyy1s = PADD(nHyy1, Hyy1p);  Hyy1p = nHyy1;
            Hxy0s = PADD(nHxy0, Hxy0p);  Hxy0p = nHxy0;
            Hxy1s = PADD(nHxy1, Hxy1p);  Hxy1p = nHxy1;

            // mu sums for next iteration's output (center col +1)
            smx0 = SHP(Sx0, Sx1); smx1 = SHP(Sx1, Sx2);
            smy0 = SHP(Sy0, Sy1); smy1 = SHP(Sy1, Sy2);
        }

        // stage-1 accumulator updates (every iteration)
        hx0s = PADD(nhx0, hx0p);  hx0p = nhx0;
        hx1s = PADD(nhx1, hx1p);  hx1p = nhx1;
        hx2s = PADD(nhx2, hx2p);  hx2p = nhx2;
        hy0s = PADD(nhy0, hy0p);  hy0p = nhy0;
        hy1s = PADD(nhy1, hy1p);  hy1p = nhy1;
        hy2s = PADD(nhy2, hy2p);  hy2p = nhy2;

        // centers for the next stage-1 row
        pXS0 = XS0; pXS1 = XS1; pXS2 = XS2;
        pYS0 = YS0; pYS1 = YS1; pYS2 = YS2;
    }
}

extern "C" void kernel_launch(void* const* d_in, const int* in_sizes, int n_in,
                              void* d_out, int out_size)
{
    const float* x = (const float*)d_in[0];
    const float* y = (const float*)d_in[1];
    float* o = (float*)d_out;

    dim3 grid((OUT_W + TILE_W - 1) / TILE_W,   // 8
              (OUT_H + TILE_H - 1) / TILE_H,   // 8
              48);                             // 16 batch * 3 channels
    ssim_kernel<<<grid, NTHREADS>>>(x, y, o);
}

// round 5
// speedup vs baseline: 2.6656x; 1.0369x over previous
#include <cuda_runtime.h>

// SSIM fully-fused, smem-free kernel for GB300 (sm_103a).
// Each thread produces a 4-column x 16-row output patch by sliding vertically,
// reading 2 float4 per input array per row directly from global. Vertical
// reuse lives in (prev, pairsum) register accumulators, all math packed f32x2.
//
// Algebra (scale-cancelled): with S = 3x3 sum, u = S - 9*center,
//   num = (2*Sx*Sy + 81*C1) * (2*Uxy + 729*C2)
//   den = (Sx^2 + Sy^2 + 81*C1) * (Uss + 729*C2),  Uss = Uxx + Uyy
// The xx and yy second-stage pipelines are merged: ss = ux^2 + uy^2 is
// pooled as ONE channel (denominator never needs the parts separately).

#define IMG_H 512
#define IMG_W 960
#define OUT_H 508
#define OUT_W 956

#define NTHREADS 128          // 32 lanes wide x 4 strips
#define STRIP_H 16
#define TILE_W 128            // 32 lanes x 4 cols
#define TILE_H 64             // 4 strips x 16 rows

typedef unsigned long long u64;

__device__ __forceinline__ u64 PK(float lo, float hi) {
    u64 r; asm("mov.b64 %0, {%1, %2};" : "=l"(r) : "f"(lo), "f"(hi)); return r;
}
__device__ __forceinline__ void UPK(u64 a, float& lo, float& hi) {
    asm("mov.b64 {%0, %1}, %2;" : "=f"(lo), "=f"(hi) : "l"(a));
}
// (a.hi, b.lo)
__device__ __forceinline__ u64 SHP(u64 a, u64 b) {
    float alo, ahi, blo, bhi; UPK(a, alo, ahi); UPK(b, blo, bhi);
    return PK(ahi, blo);
}
__device__ __forceinline__ u64 PADD(u64 a, u64 b) {
    u64 r; asm("add.rn.f32x2 %0, %1, %2;" : "=l"(r) : "l"(a), "l"(b)); return r;
}
__device__ __forceinline__ u64 PMUL(u64 a, u64 b) {
    u64 r; asm("mul.rn.f32x2 %0, %1, %2;" : "=l"(r) : "l"(a), "l"(b)); return r;
}
__device__ __forceinline__ u64 PFMA(u64 a, u64 b, u64 c) {
    u64 r; asm("fma.rn.f32x2 %0, %1, %2, %3;" : "=l"(r) : "l"(a), "l"(b), "l"(c)); return r;
}
#define PREF_L2(p) asm volatile("prefetch.global.L2 [%0];" :: "l"(p))

__global__ __launch_bounds__(NTHREADS, 5)
void ssim_kernel(const float* __restrict__ X,
                 const float* __restrict__ Y,
                 float* __restrict__ O)
{
    const int tid   = threadIdx.x;
    const int lane  = tid & 31;
    const int strip = tid >> 5;
    const int img   = blockIdx.z;
    const int oy0   = blockIdx.y * TILE_H + strip * STRIP_H;
    const int ox    = blockIdx.x * TILE_W + 4 * lane;
    // Clamp read base so edge threads stay in-bounds (outputs masked later).
    const int cx    = min(ox, IMG_W - 8);

    const float* __restrict__ Xb = X + (size_t)img * (IMG_H * IMG_W) + cx;
    const float* __restrict__ Yb = Y + (size_t)img * (IMG_H * IMG_W) + cx;
    float* __restrict__ Ob = O + (size_t)img * (OUT_H * OUT_W);

    const u64 c_m9    = PK(-9.0f, -9.0f);
    const u64 c_two   = PK(2.0f, 2.0f);
    const u64 c_81c1  = PK(8.1e-3f, 8.1e-3f);     // 81 * 0.01^2
    const u64 c_729c2 = PK(0.6561f, 0.6561f);     // 729 * 0.03^2

    // (prev, pairsum) accumulators: running vertical 3-sum state, 2 regs each.
    u64 hx0p = 0, hx0s = 0, hx1p = 0, hx1s = 0, hx2p = 0, hx2s = 0;
    u64 hy0p = 0, hy0s = 0, hy1p = 0, hy1s = 0, hy2p = 0, hy2s = 0;
    u64 Hss0p = 0, Hss0s = 0, Hss1p = 0, Hss1s = 0;   // merged xx+yy channel
    u64 Hxy0p = 0, Hxy0s = 0, Hxy1p = 0, Hxy1s = 0;
    // Previous-row shifted pairs (centers for u = S - 9*c).
    u64 pXS0 = 0, pXS1 = 0, pXS2 = 0, pYS0 = 0, pYS1 = 0, pYS2 = 0;
    // mu sums from previous stage-1 row.
    u64 smx0 = 0, smx1 = 0, smy0 = 0, smy1 = 0;

    #pragma unroll
    for (int t = 0; t < STRIP_H + 4; ++t) {
        const int gy = min(oy0 + t, IMG_H - 1);
        const size_t roff = (size_t)gy * IMG_W;

        float4 xa = __ldg((const float4*)(Xb + roff));
        float4 xb = __ldg((const float4*)(Xb + roff) + 1);
        float4 ya = __ldg((const float4*)(Yb + roff));
        float4 yb = __ldg((const float4*)(Yb + roff) + 1);

        if (t + 4 < STRIP_H + 4) {   // compile-time under full unroll
            // Unclamped address: prefetch to an invalid address is ignored.
            const size_t poff = roff + 4 * (size_t)IMG_W;
            PREF_L2(Xb + poff);
            PREF_L2(Yb + poff);
        }

        // natural pairs P_i = (v2i, v2i+1), shifted S_i = (v2i+1, v2i+2)
        u64 XP0 = PK(xa.x, xa.y), XS0 = PK(xa.y, xa.z), XP1 = PK(xa.z, xa.w);
        u64 XS1 = PK(xa.w, xb.x), XP2 = PK(xb.x, xb.y), XS2 = PK(xb.y, xb.z);
        u64 XP3 = PK(xb.z, xb.w);
        u64 YP0 = PK(ya.x, ya.y), YS0 = PK(ya.y, ya.z), YP1 = PK(ya.z, ya.w);
        u64 YS1 = PK(ya.w, yb.x), YP2 = PK(yb.x, yb.y), YS2 = PK(yb.y, yb.z);
        u64 YP3 = PK(yb.z, yb.w);

        // horizontal 3-sums at stage-1 col pairs (0,1),(2,3),(4,5)
        u64 nhx0 = PADD(PADD(XP0, XS0), XP1);
        u64 nhx1 = PADD(PADD(XP1, XS1), XP2);
        u64 nhx2 = PADD(PADD(XP2, XS2), XP3);
        u64 nhy0 = PADD(PADD(YP0, YS0), YP1);
        u64 nhy1 = PADD(PADD(YP1, YS1), YP2);
        u64 nhy2 = PADD(PADD(YP2, YS2), YP3);

        if (t >= 2) {
            // stage-1 vertical 3-sums: S = h_t + (h_{t-1} + h_{t-2})
            u64 Sx0 = PADD(nhx0, hx0s);
            u64 Sx1 = PADD(nhx1, hx1s);
            u64 Sx2 = PADD(nhx2, hx2s);
            u64 Sy0 = PADD(nhy0, hy0s);
            u64 Sy1 = PADD(nhy1, hy1s);
            u64 Sy2 = PADD(nhy2, hy2s);

            // u = S - 9*center (centers = prev row shifted pairs)
            u64 ux0 = PFMA(pXS0, c_m9, Sx0);
            u64 ux1 = PFMA(pXS1, c_m9, Sx1);
            u64 ux2 = PFMA(pXS2, c_m9, Sx2);
            u64 uy0 = PFMA(pYS0, c_m9, Sy0);
            u64 uy1 = PFMA(pYS1, c_m9, Sy1);
            u64 uy2 = PFMA(pYS2, c_m9, Sy2);

            // merged channel ss = ux^2 + uy^2; cross channel xy = ux*uy
            u64 tss0 = PFMA(uy0, uy0, PMUL(ux0, ux0));
            u64 tss1 = PFMA(uy1, uy1, PMUL(ux1, ux1));
            u64 tss2 = PFMA(uy2, uy2, PMUL(ux2, ux2));
            u64 txy0 = PMUL(ux0, uy0);
            u64 txy1 = PMUL(ux1, uy1);
            u64 txy2 = PMUL(ux2, uy2);

            // stage-2 horizontal 3-sums for output pairs (0,1) and (2,3)
            u64 nHss0 = PADD(PADD(tss0, SHP(tss0, tss1)), tss1);
            u64 nHss1 = PADD(PADD(tss1, SHP(tss1, tss2)), tss2);
            u64 nHxy0 = PADD(PADD(txy0, SHP(txy0, txy1)), txy1);
            u64 nHxy1 = PADD(PADD(txy1, SHP(txy1, txy2)), txy2);

            if (t >= 4) {
                // stage-2 vertical 3-sums: U = H_t + (H_{t-1} + H_{t-2})
                u64 Uss0 = PADD(nHss0, Hss0s);
                u64 Uss1 = PADD(nHss1, Hss1s);
                u64 Uxy0 = PADD(nHxy0, Hxy0s);
                u64 Uxy1 = PADD(nHxy1, Hxy1s);

                // mu sums from previous iteration (stage-1 row o+1)
                u64 n1a = PFMA(PMUL(smx0, smy0), c_two, c_81c1);
                u64 d1a = PFMA(smy0, smy0, PFMA(smx0, smx0, c_81c1));
                u64 n1b = PFMA(PMUL(smx1, smy1), c_two, c_81c1);
                u64 d1b = PFMA(smy1, smy1, PFMA(smx1, smx1, c_81c1));

                u64 n2a = PFMA(Uxy0, c_two, c_729c2);
                u64 d2a = PADD(Uss0, c_729c2);
                u64 n2b = PFMA(Uxy1, c_two, c_729c2);
                u64 d2b = PADD(Uss1, c_729c2);

                u64 numa = PMUL(n1a, n2a), dena = PMUL(d1a, d2a);
                u64 numb = PMUL(n1b, n2b), denb = PMUL(d1b, d2b);

                float n0, n1, n2, n3, d0, d1, d2, d3;
                UPK(numa, n0, n1); UPK(numb, n2, n3);
                UPK(dena, d0, d1); UPK(denb, d2, d3);
                float4 out;
                out.x = fminf(fmaxf(1.0f - __fdividef(n0, d0), 0.0f), 2.0f);
                out.y = fminf(fmaxf(1.0f - __fdividef(n1, d1), 0.0f), 2.0f);
                out.z = fminf(fmaxf(1.0f - __fdividef(n2, d2), 0.0f), 2.0f);
                out.w = fminf(fmaxf(1.0f - __fdividef(n3, d3), 0.0f), 2.0f);

                const int oy = oy0 + t - 4;
                if (oy < OUT_H && ox < OUT_W) {
                    *(float4*)(Ob + (size_t)oy * OUT_W + ox) = out;
                }
            }

            // stage-2 accumulator updates
            Hss0s = PADD(nHss0, Hss0p);  Hss0p = nHss0;
            Hss1s = PADD(nHss1, Hss1p);  Hss1p = nHss1;
            Hxy0s = PADD(nHxy0, Hxy0p);  Hxy0p = nHxy0;
            Hxy1s = PADD(nHxy1, Hxy1p);  Hxy1p = nHxy1;

            // mu sums for next iteration's output (center col +1)
            smx0 = SHP(Sx0, Sx1); smx1 = SHP(Sx1, Sx2);
            smy0 = SHP(Sy0, Sy1); smy1 = SHP(Sy1, Sy2);
        }

        // stage-1 accumulator updates (every iteration)
        hx0s = PADD(nhx0, hx0p);  hx0p = nhx0;
        hx1s = PADD(nhx1, hx1p);  hx1p = nhx1;
        hx2s = PADD(nhx2, hx2p);  hx2p = nhx2;
        hy0s = PADD(nhy0, hy0p);  hy0p = nhy0;
        hy1s = PADD(nhy1, hy1p);  hy1p = nhy1;
        hy2s = PADD(nhy2, hy2p);  hy2p = nhy2;

        // centers for the next stage-1 row
        pXS0 = XS0; pXS1 = XS1; pXS2 = XS2;
        pYS0 = YS0; pYS1 = YS1; pYS2 = YS2;
    }
}

extern "C" void kernel_launch(void* const* d_in, const int* in_sizes, int n_in,
                              void* d_out, int out_size)
{
    const float* x = (const float*)d_in[0];
    const float* y = (const float*)d_in[1];
    float* o = (float*)d_out;

    dim3 grid((OUT_W + TILE_W - 1) / TILE_W,   // 8
              (OUT_H + TILE_H - 1) / TILE_H,   // 8
              48);                             // 16 batch * 3 channels
    ssim_kernel<<<grid, NTHREADS>>>(x, y, o);
}